// round 2
// baseline (speedup 1.0000x reference)
#include <cuda_runtime.h>

#define EPSK 1e-7f

typedef unsigned long long u64;

constexpr int Bn = 2, Hh = 192, Ww = 192, HQ = 384;

// ---- packed f32x2 helpers (sm_103a) ---------------------------------------
__device__ __forceinline__ u64 pack2(float lo, float hi) {
    u64 r; asm("mov.b64 %0,{%1,%2};" : "=l"(r) : "f"(lo), "f"(hi)); return r;
}
__device__ __forceinline__ void unpack2(float& lo, float& hi, u64 v) {
    asm("mov.b64 {%0,%1},%2;" : "=f"(lo), "=f"(hi) : "l"(v));
}
__device__ __forceinline__ void fma2(u64& d, u64 a, u64 b) {
    asm("fma.rn.f32x2 %0,%1,%2,%0;" : "+l"(d) : "l"(a), "l"(b));
}

// Scratch (no allocations allowed -> __device__ globals)
__device__ float g_a4[Bn * 96 * 96 * 32];
__device__ float g_a32[Bn * 24 * 24 * 32];
__device__ float g_X[Bn * Hh * Ww * 96];     // concat of a2 | up(a4) | up(a32)
__device__ float g_aspp[Bn * Hh * Ww * 96];  // conv3x3 output
__device__ float g_P[Bn * Hh * Ww * 64];     // aspp @ mw0[:96] + mb0

// ---------------------------------------------------------------------------
// 1x1 conv + ReLU. One warp per pixel, lane = output channel (Cout == 32).
// ---------------------------------------------------------------------------
__global__ void conv1x1_kernel(const float* __restrict__ in, const float* __restrict__ w,
                               const float* __restrict__ bias, float* __restrict__ out,
                               int npix, int Cin, int outStride, int outOff)
{
    extern __shared__ float ws[];  // Cin*32 floats
    int tid = threadIdx.x;
    for (int i = tid; i < Cin * 32; i += blockDim.x) ws[i] = w[i];
    __syncthreads();
    int warp = tid >> 5, lane = tid & 31;
    int p = blockIdx.x * (blockDim.x >> 5) + warp;
    if (p >= npix) return;
    const float* ip = in + (size_t)p * Cin;
    float acc = bias[lane];
#pragma unroll 4
    for (int k = 0; k < Cin; k++) acc += ip[k] * ws[k * 32 + lane];
    out[(size_t)p * outStride + outOff + lane] = fmaxf(acc, 0.0f);
}

// ---------------------------------------------------------------------------
// Bilinear upsample (half-pixel centers, edge clamp) of a 32-channel map to
// 192x192, written into the concat buffer at chOff.
// ---------------------------------------------------------------------------
__global__ void upsample_kernel(const float* __restrict__ in, float* __restrict__ X,
                                int inH, int inW, int chOff)
{
    int idx = blockIdx.x * blockDim.x + threadIdx.x;  // Bn*Hh*Ww*8 exact
    int c4 = idx & 7;
    int pix = idx >> 3;
    int x = pix % Ww;
    int t = pix / Ww;
    int y = t % Hh;
    int b = t / Hh;

    float sy = (y + 0.5f) * (float)inH / (float)Hh - 0.5f;
    float sx = (x + 0.5f) * (float)inW / (float)Ww - 0.5f;
    float fy0 = floorf(sy), fx0 = floorf(sx);
    float fy = sy - fy0, fx = sx - fx0;
    int y0 = (int)fy0, x0 = (int)fx0;
    int y1 = min(y0 + 1, inH - 1), x1 = min(x0 + 1, inW - 1);
    y0 = max(y0, 0);
    x0 = max(x0, 0);

    const float4* ip = (const float4*)in;
    float4 v00 = ip[(((size_t)b * inH + y0) * inW + x0) * 8 + c4];
    float4 v01 = ip[(((size_t)b * inH + y0) * inW + x1) * 8 + c4];
    float4 v10 = ip[(((size_t)b * inH + y1) * inW + x0) * 8 + c4];
    float4 v11 = ip[(((size_t)b * inH + y1) * inW + x1) * 8 + c4];
    float w00 = (1.f - fy) * (1.f - fx), w01 = (1.f - fy) * fx;
    float w10 = fy * (1.f - fx), w11 = fy * fx;
    float4 r;
    r.x = v00.x * w00 + v01.x * w01 + v10.x * w10 + v11.x * w11;
    r.y = v00.y * w00 + v01.y * w01 + v10.y * w10 + v11.y * w11;
    r.z = v00.z * w00 + v01.z * w01 + v10.z * w10 + v11.z * w11;
    r.w = v00.w * w00 + v01.w * w01 + v10.w * w10 + v11.w * w11;
    *(float4*)(X + (((size_t)b * Hh + y) * Ww + x) * 96 + chOff + c4 * 4) = r;
}

// ---------------------------------------------------------------------------
// 3x3 conv (zero pad SAME) 96->96 + bias + ReLU, packed-f32x2 over oc pairs.
// Block: 128 threads = 16 oc-pairs x 8 rows; tile 8x8 spatial x 32 oc.
// in_s layout [ic][ry*12+rx] so spatial is contiguous (float2 loads);
// weight pairs (2*ocp, 2*ocp+1) contiguous -> LDS.64 conflict-free.
// ---------------------------------------------------------------------------
__global__ void __launch_bounds__(128)
conv3x3_kernel(const float* __restrict__ X, const float* __restrict__ wf,
               const float* __restrict__ bf, float* __restrict__ out)
{
    __shared__ float in_s[16 * 120];   // [ic][ry*12 + rx], ry,rx in 0..9
    __shared__ float ws[9 * 16 * 32];  // [kk][ic][oc]
    int tx0 = blockIdx.x * 8, ty0 = blockIdx.y * 8;
    int b = blockIdx.z / 3, ocg = blockIdx.z % 3;
    int tid = threadIdx.x;
    int ocp = tid & 15;   // oc pair -> oc = 2*ocp, 2*ocp+1
    int row = tid >> 4;   // 0..7

    u64 acc[8];
#pragma unroll
    for (int i = 0; i < 8; i++) acc[i] = 0ull;

#pragma unroll 1
    for (int icc = 0; icc < 6; icc++) {
        int icb = icc * 16;
        __syncthreads();
        // input tile 10x10x16 (zero padded)
        for (int i = tid; i < 1600; i += 128) {
            int ic = i & 15;
            int rp = i >> 4;
            int rx = rp % 10, ry = rp / 10;
            int gy = ty0 + ry - 1, gx = tx0 + rx - 1;
            float v = 0.0f;
            if ((unsigned)gy < (unsigned)Hh && (unsigned)gx < (unsigned)Ww)
                v = X[(((size_t)b * Hh + gy) * Ww + gx) * 96 + icb + ic];
            in_s[ic * 120 + ry * 12 + rx] = v;
        }
        // weights 9x16x32
        for (int i = tid; i < 4608; i += 128) {
            int o = i & 31;
            int r = i >> 5;
            int ic = r & 15;
            int kk = r >> 4;  // 0..8 == dy*3+dx
            ws[i] = wf[((size_t)kk * 96 + icb + ic) * 96 + ocg * 32 + o];
        }
        __syncthreads();
#pragma unroll
        for (int dy = 0; dy < 3; dy++) {
#pragma unroll
            for (int ic = 0; ic < 16; ic++) {
                const float2* xrow = (const float2*)(in_s + ic * 120 + (row + dy) * 12);
                float2 xab[5];
#pragma unroll
                for (int t = 0; t < 5; t++) xab[t] = xrow[t];
                float xr[10];
#pragma unroll
                for (int t = 0; t < 5; t++) { xr[2 * t] = xab[t].x; xr[2 * t + 1] = xab[t].y; }
                u64 xp[10];
#pragma unroll
                for (int t = 0; t < 10; t++) xp[t] = pack2(xr[t], xr[t]);
#pragma unroll
                for (int dx = 0; dx < 3; dx++) {
                    u64 wv = *(const u64*)(ws + ((dy * 3 + dx) * 16 + ic) * 32 + 2 * ocp);
#pragma unroll
                    for (int col = 0; col < 8; col++) fma2(acc[col], xp[col + dx], wv);
                }
            }
        }
    }
    float bb0 = bf[ocg * 32 + 2 * ocp];
    float bb1 = bf[ocg * 32 + 2 * ocp + 1];
#pragma unroll
    for (int col = 0; col < 8; col++) {
        int gy = ty0 + row, gx = tx0 + col;
        float a, c;
        unpack2(a, c, acc[col]);
        float2 r;
        r.x = fmaxf(a + bb0, 0.0f);
        r.y = fmaxf(c + bb1, 0.0f);
        *(float2*)(out + (((size_t)b * Hh + gy) * Ww + gx) * 96 + ocg * 32 + 2 * ocp) = r;
    }
}

// ---------------------------------------------------------------------------
// Per-pixel MLP-layer-1 feature projection: P = aspp @ mw0[0:96] + mb0.
// One warp per pixel; lane computes outputs (lane, lane+32).
// ---------------------------------------------------------------------------
__global__ void proj_kernel(const float* __restrict__ aspp, const float* __restrict__ mw0,
                            const float* __restrict__ mb0, float* __restrict__ P)
{
    __shared__ float ws[96 * 64];
    int tid = threadIdx.x;
    for (int i = tid; i < 96 * 64; i += 256) ws[i] = mw0[i];
    __syncthreads();
    int warp = tid >> 5, lane = tid & 31;
    int p = blockIdx.x * 8 + warp;  // 73728 pixels = 9216 blocks * 8
    const float* ip = aspp + (size_t)p * 96;
    float a0 = mb0[lane], a1 = mb0[lane + 32];
#pragma unroll 4
    for (int k = 0; k < 96; k++) {
        float x = ip[k];
        a0 += x * ws[k * 64 + lane];
        a1 += x * ws[k * 64 + lane + 32];
    }
    P[(size_t)p * 64 + lane] = a0;
    P[(size_t)p * 64 + lane + 32] = a1;
}

// ---------------------------------------------------------------------------
// Decode: one thread per query. 4 corners: nearest gather of projected P,
// add the 6 "extra" input contributions via mw0[96:102], ReLU, 64x64 layer
// (packed f32x2: 2 MACs/issue), 64->1 layer, area-weighted blend.
// ---------------------------------------------------------------------------
__global__ void __launch_bounds__(256)
decode_kernel(const float* __restrict__ P, const float* __restrict__ coords,
              const float* __restrict__ cells, const float* __restrict__ mw0,
              const float* __restrict__ mw1, const float* __restrict__ mb1,
              const float* __restrict__ mw2, const float* __restrict__ mb2,
              float* __restrict__ out)
{
    __shared__ __align__(16) float sw1[64 * 64];
    __shared__ __align__(16) float sw0e[6 * 64];
    __shared__ __align__(16) float sb1[64];
    __shared__ float sw2[64];
    __shared__ float sb2s;
    int tid = threadIdx.x;
    for (int i = tid; i < 64 * 64; i += 256) sw1[i] = mw1[i];
    for (int i = tid; i < 6 * 64; i += 256) sw0e[i] = mw0[96 * 64 + i];
    if (tid < 64) { sb1[tid] = mb1[tid]; sw2[tid] = mw2[tid]; }
    if (tid == 0) sb2s = mb2[0];
    __syncthreads();

    int q = blockIdx.x * 256 + tid;  // 294912 = 1152 * 256 exact
    int b = q / (HQ * HQ);
    float cy = coords[2 * q], cx = coords[2 * q + 1];
    float clh = cells[2 * q] * (float)Hh, clw = cells[2 * q + 1] * (float)Ww;
    const float rr = 1.0f / (float)Hh;

    float preds[4], areas[4];
#pragma unroll 1
    for (int corner = 0; corner < 4; corner++) {
        float vy = (corner & 2) ? 1.0f : -1.0f;
        float vx = (corner & 1) ? 1.0f : -1.0f;
        float ccy = fminf(fmaxf(cy + vy * rr + EPSK, -1.0f + EPSK), 1.0f - EPSK);
        float ccx = fminf(fmaxf(cx + vx * rr + EPSK, -1.0f + EPSK), 1.0f - EPSK);
        int iy = (int)rintf((ccy + 1.0f) * (float)Hh / 2.0f - 0.5f);
        int ix = (int)rintf((ccx + 1.0f) * (float)Ww / 2.0f - 0.5f);
        iy = min(max(iy, 0), Hh - 1);
        ix = min(max(ix, 0), Ww - 1);
        float sampy = ((iy + 0.5f) / (float)Hh) * 2.0f - 1.0f;
        float sampx = ((ix + 0.5f) / (float)Ww) * 2.0f - 1.0f;
        float rely = (cy - sampy) * (float)Hh;
        float relx = (cx - sampx) * (float)Ww;

        // h0 = gathered P + extras (packed pairs over output index)
        u64 h0p[32];
        const ulonglong2* p4 =
            (const ulonglong2*)(P + (((size_t)b * Hh + iy) * Ww + ix) * 64);
#pragma unroll
        for (int j = 0; j < 16; j++) {
            ulonglong2 v = p4[j];
            h0p[2 * j] = v.x;
            h0p[2 * j + 1] = v.y;
        }
        float xs[6] = {rely, relx, cy, cx, clh, clw};
#pragma unroll
        for (int e = 0; e < 6; e++) {
            u64 xp = pack2(xs[e], xs[e]);
            const ulonglong2* wp = (const ulonglong2*)(sw0e + e * 64);
#pragma unroll
            for (int j = 0; j < 16; j++) {
                ulonglong2 w = wp[j];
                fma2(h0p[2 * j], xp, w.x);
                fma2(h0p[2 * j + 1], xp, w.y);
            }
        }
        // layer 2: h1 = b1 + relu(h0) @ w1   (pairs over j, 2 k per iter)
        u64 h1p[32];
        const ulonglong2* bp = (const ulonglong2*)sb1;
#pragma unroll
        for (int j = 0; j < 16; j++) {
            ulonglong2 v = bp[j];
            h1p[2 * j] = v.x;
            h1p[2 * j + 1] = v.y;
        }
#pragma unroll 4
        for (int kp = 0; kp < 32; kp++) {
            float lo, hi;
            unpack2(lo, hi, h0p[kp]);
            float xa = fmaxf(lo, 0.0f), xb = fmaxf(hi, 0.0f);
            u64 xpa = pack2(xa, xa), xpb = pack2(xb, xb);
            const ulonglong2* wra = (const ulonglong2*)(sw1 + (2 * kp) * 64);
            const ulonglong2* wrb = (const ulonglong2*)(sw1 + (2 * kp + 1) * 64);
#pragma unroll
            for (int j = 0; j < 16; j++) {
                ulonglong2 w = wra[j];
                fma2(h1p[2 * j], xpa, w.x);
                fma2(h1p[2 * j + 1], xpa, w.y);
            }
#pragma unroll
            for (int j = 0; j < 16; j++) {
                ulonglong2 w = wrb[j];
                fma2(h1p[2 * j], xpb, w.x);
                fma2(h1p[2 * j + 1], xpb, w.y);
            }
        }
        float pr = sb2s;
#pragma unroll
        for (int j = 0; j < 32; j++) {
            float a, c;
            unpack2(a, c, h1p[j]);
            pr += fmaxf(a, 0.0f) * sw2[2 * j] + fmaxf(c, 0.0f) * sw2[2 * j + 1];
        }
        preds[corner] = pr;
        areas[corner] = fabsf(rely * relx) + EPSK;
    }
    float num = preds[0] * areas[3] + preds[1] * areas[2] +
                preds[2] * areas[1] + preds[3] * areas[0];
    float den = areas[0] + areas[1] + areas[2] + areas[3];
    out[q] = num / den;
}

// ---------------------------------------------------------------------------
extern "C" void kernel_launch(void* const* d_in, const int* in_sizes, int n_in,
                              void* d_out, int out_size)
{
    const float* feats2  = (const float*)d_in[0];
    const float* feats4  = (const float*)d_in[1];
    const float* feats32 = (const float*)d_in[2];
    const float* coords  = (const float*)d_in[3];
    const float* cells   = (const float*)d_in[4];
    const float* w2  = (const float*)d_in[5];
    const float* b2  = (const float*)d_in[6];
    const float* w4  = (const float*)d_in[7];
    const float* b4  = (const float*)d_in[8];
    const float* w32 = (const float*)d_in[9];
    const float* b32 = (const float*)d_in[10];
    const float* wf  = (const float*)d_in[11];
    const float* bf  = (const float*)d_in[12];
    const float* mw0 = (const float*)d_in[13];
    const float* mb0 = (const float*)d_in[14];
    const float* mw1 = (const float*)d_in[15];
    const float* mb1 = (const float*)d_in[16];
    const float* mw2 = (const float*)d_in[17];
    const float* mb2 = (const float*)d_in[18];
    float* out = (float*)d_out;

    float *a4p, *a32p, *Xp, *asppp, *Pp;
    cudaGetSymbolAddress((void**)&a4p, g_a4);
    cudaGetSymbolAddress((void**)&a32p, g_a32);
    cudaGetSymbolAddress((void**)&Xp, g_X);
    cudaGetSymbolAddress((void**)&asppp, g_aspp);
    cudaGetSymbolAddress((void**)&Pp, g_P);

    // 1x1 convs (a2 goes straight into the concat buffer, channels 0..31)
    conv1x1_kernel<<<9216, 256, 64 * 32 * 4>>>(feats2, w2, b2, Xp, 73728, 64, 96, 0);
    conv1x1_kernel<<<2304, 256, 96 * 32 * 4>>>(feats4, w4, b4, a4p, 18432, 96, 32, 0);
    conv1x1_kernel<<<144, 256, 160 * 32 * 4>>>(feats32, w32, b32, a32p, 1152, 160, 32, 0);

    // bilinear upsample into concat channels 32..63 and 64..95
    upsample_kernel<<<2304, 256>>>(a4p, Xp, 96, 96, 32);
    upsample_kernel<<<2304, 256>>>(a32p, Xp, 24, 24, 64);

    // 3x3 conv + ReLU (packed f32x2)
    dim3 g3(24, 24, 6);
    conv3x3_kernel<<<g3, 128>>>(Xp, wf, bf, asppp);

    // per-pixel projection through MLP layer-1 feature block
    proj_kernel<<<9216, 256>>>(asppp, mw0, mb0, Pp);

    // per-query 4-corner decode + blend (packed f32x2)
    decode_kernel<<<1152, 256>>>(Pp, coords, cells, mw0, mw1, mb1, mw2, mb2, out);
}

// round 3
// speedup vs baseline: 1.0704x; 1.0704x over previous
#include <cuda_runtime.h>

#define EPSK 1e-7f

typedef unsigned long long u64;

constexpr int Bn = 2, Hh = 192, Ww = 192, HQ = 384;

// ---- packed f32x2 helpers (sm_103a) ---------------------------------------
__device__ __forceinline__ u64 pack2(float lo, float hi) {
    u64 r; asm("mov.b64 %0,{%1,%2};" : "=l"(r) : "f"(lo), "f"(hi)); return r;
}
__device__ __forceinline__ void unpack2(float& lo, float& hi, u64 v) {
    asm("mov.b64 {%0,%1},%2;" : "=f"(lo), "=f"(hi) : "l"(v));
}
__device__ __forceinline__ void fma2(u64& d, u64 a, u64 b) {
    asm("fma.rn.f32x2 %0,%1,%2,%0;" : "+l"(d) : "l"(a), "l"(b));
}

// Scratch (no allocations allowed -> __device__ globals)
__device__ float g_a4[Bn * 96 * 96 * 32];
__device__ float g_a32[Bn * 24 * 24 * 32];
__device__ float g_X[Bn * Hh * Ww * 96];     // concat of a2 | up(a4) | up(a32)
__device__ float g_aspp[Bn * Hh * Ww * 96];  // conv3x3 output
__device__ float g_P[Bn * Hh * Ww * 64];     // aspp @ mw0[:96] + mb0

// ---------------------------------------------------------------------------
// 1x1 conv + ReLU. One warp per pixel, lane = output channel (Cout == 32).
// ---------------------------------------------------------------------------
__global__ void conv1x1_kernel(const float* __restrict__ in, const float* __restrict__ w,
                               const float* __restrict__ bias, float* __restrict__ out,
                               int npix, int Cin, int outStride, int outOff)
{
    extern __shared__ float ws[];  // Cin*32 floats
    int tid = threadIdx.x;
    for (int i = tid; i < Cin * 32; i += blockDim.x) ws[i] = w[i];
    __syncthreads();
    int warp = tid >> 5, lane = tid & 31;
    int p = blockIdx.x * (blockDim.x >> 5) + warp;
    if (p >= npix) return;
    const float* ip = in + (size_t)p * Cin;
    float acc = bias[lane];
#pragma unroll 4
    for (int k = 0; k < Cin; k++) acc += ip[k] * ws[k * 32 + lane];
    out[(size_t)p * outStride + outOff + lane] = fmaxf(acc, 0.0f);
}

// ---------------------------------------------------------------------------
// Bilinear upsample (half-pixel centers, edge clamp) of a 32-channel map to
// 192x192, written into the concat buffer at chOff.
// ---------------------------------------------------------------------------
__global__ void upsample_kernel(const float* __restrict__ in, float* __restrict__ X,
                                int inH, int inW, int chOff)
{
    int idx = blockIdx.x * blockDim.x + threadIdx.x;  // Bn*Hh*Ww*8 exact
    int c4 = idx & 7;
    int pix = idx >> 3;
    int x = pix % Ww;
    int t = pix / Ww;
    int y = t % Hh;
    int b = t / Hh;

    float sy = (y + 0.5f) * (float)inH / (float)Hh - 0.5f;
    float sx = (x + 0.5f) * (float)inW / (float)Ww - 0.5f;
    float fy0 = floorf(sy), fx0 = floorf(sx);
    float fy = sy - fy0, fx = sx - fx0;
    int y0 = (int)fy0, x0 = (int)fx0;
    int y1 = min(y0 + 1, inH - 1), x1 = min(x0 + 1, inW - 1);
    y0 = max(y0, 0);
    x0 = max(x0, 0);

    const float4* ip = (const float4*)in;
    float4 v00 = ip[(((size_t)b * inH + y0) * inW + x0) * 8 + c4];
    float4 v01 = ip[(((size_t)b * inH + y0) * inW + x1) * 8 + c4];
    float4 v10 = ip[(((size_t)b * inH + y1) * inW + x0) * 8 + c4];
    float4 v11 = ip[(((size_t)b * inH + y1) * inW + x1) * 8 + c4];
    float w00 = (1.f - fy) * (1.f - fx), w01 = (1.f - fy) * fx;
    float w10 = fy * (1.f - fx), w11 = fy * fx;
    float4 r;
    r.x = v00.x * w00 + v01.x * w01 + v10.x * w10 + v11.x * w11;
    r.y = v00.y * w00 + v01.y * w01 + v10.y * w10 + v11.y * w11;
    r.z = v00.z * w00 + v01.z * w01 + v10.z * w10 + v11.z * w11;
    r.w = v00.w * w00 + v01.w * w01 + v10.w * w10 + v11.w * w11;
    *(float4*)(X + (((size_t)b * Hh + y) * Ww + x) * 96 + chOff + c4 * 4) = r;
}

// ---------------------------------------------------------------------------
// 3x3 conv (zero pad SAME) 96->96 + bias + ReLU, packed-f32x2 over oc pairs.
// Block: 256 threads = 16 oc-pairs x 16 rows; tile 16x8 spatial x 32 oc.
// in_s layout [ic][ry*12+rx] so spatial is contiguous (float2 loads);
// weight pairs (2*ocp, 2*ocp+1) contiguous -> LDS.64 conflict-free.
// ---------------------------------------------------------------------------
__global__ void __launch_bounds__(256)
conv3x3_kernel(const float* __restrict__ X, const float* __restrict__ wf,
               const float* __restrict__ bf, float* __restrict__ out)
{
    __shared__ float in_s[16 * 216];   // [ic][ry*12 + rx], ry 0..17, rx 0..9
    __shared__ float ws[9 * 16 * 32];  // [kk][ic][oc]
    int tx0 = blockIdx.x * 8, ty0 = blockIdx.y * 16;
    int b = blockIdx.z / 3, ocg = blockIdx.z % 3;
    int tid = threadIdx.x;
    int ocp = tid & 15;   // oc pair -> oc = 2*ocp, 2*ocp+1
    int row = tid >> 4;   // 0..15

    u64 acc[8];
#pragma unroll
    for (int i = 0; i < 8; i++) acc[i] = 0ull;

#pragma unroll 1
    for (int icc = 0; icc < 6; icc++) {
        int icb = icc * 16;
        __syncthreads();
        // input tile 18x10x16 (zero padded)
        for (int i = tid; i < 2880; i += 256) {
            int ic = i & 15;
            int rp = i >> 4;          // 0..179
            int rx = rp % 10, ry = rp / 10;
            int gy = ty0 + ry - 1, gx = tx0 + rx - 1;
            float v = 0.0f;
            if ((unsigned)gy < (unsigned)Hh && (unsigned)gx < (unsigned)Ww)
                v = X[(((size_t)b * Hh + gy) * Ww + gx) * 96 + icb + ic];
            in_s[ic * 216 + ry * 12 + rx] = v;
        }
        // weights 9x16x32
        for (int i = tid; i < 4608; i += 256) {
            int o = i & 31;
            int r = i >> 5;
            int ic = r & 15;
            int kk = r >> 4;  // 0..8 == dy*3+dx
            ws[i] = wf[((size_t)kk * 96 + icb + ic) * 96 + ocg * 32 + o];
        }
        __syncthreads();
#pragma unroll
        for (int dy = 0; dy < 3; dy++) {
#pragma unroll
            for (int ic = 0; ic < 16; ic++) {
                const float2* xrow = (const float2*)(in_s + ic * 216 + (row + dy) * 12);
                float2 xab[5];
#pragma unroll
                for (int t = 0; t < 5; t++) xab[t] = xrow[t];
                float xr[10];
#pragma unroll
                for (int t = 0; t < 5; t++) { xr[2 * t] = xab[t].x; xr[2 * t + 1] = xab[t].y; }
                u64 xp[10];
#pragma unroll
                for (int t = 0; t < 10; t++) xp[t] = pack2(xr[t], xr[t]);
#pragma unroll
                for (int dx = 0; dx < 3; dx++) {
                    u64 wv = *(const u64*)(ws + ((dy * 3 + dx) * 16 + ic) * 32 + 2 * ocp);
#pragma unroll
                    for (int col = 0; col < 8; col++) fma2(acc[col], xp[col + dx], wv);
                }
            }
        }
    }
    float bb0 = bf[ocg * 32 + 2 * ocp];
    float bb1 = bf[ocg * 32 + 2 * ocp + 1];
#pragma unroll
    for (int col = 0; col < 8; col++) {
        int gy = ty0 + row, gx = tx0 + col;
        float a, c;
        unpack2(a, c, acc[col]);
        float2 r;
        r.x = fmaxf(a + bb0, 0.0f);
        r.y = fmaxf(c + bb1, 0.0f);
        *(float2*)(out + (((size_t)b * Hh + gy) * Ww + gx) * 96 + ocg * 32 + 2 * ocp) = r;
    }
}

// ---------------------------------------------------------------------------
// Per-pixel MLP-layer-1 feature projection: P = aspp @ mw0[0:96] + mb0.
// One warp per pixel; lane computes outputs (lane, lane+32).
// ---------------------------------------------------------------------------
__global__ void proj_kernel(const float* __restrict__ aspp, const float* __restrict__ mw0,
                            const float* __restrict__ mb0, float* __restrict__ P)
{
    __shared__ float ws[96 * 64];
    int tid = threadIdx.x;
    for (int i = tid; i < 96 * 64; i += 256) ws[i] = mw0[i];
    __syncthreads();
    int warp = tid >> 5, lane = tid & 31;
    int p = blockIdx.x * 8 + warp;  // 73728 pixels = 9216 blocks * 8
    const float* ip = aspp + (size_t)p * 96;
    float a0 = mb0[lane], a1 = mb0[lane + 32];
#pragma unroll 4
    for (int k = 0; k < 96; k++) {
        float x = ip[k];
        a0 += x * ws[k * 64 + lane];
        a1 += x * ws[k * 64 + lane + 32];
    }
    P[(size_t)p * 64 + lane] = a0;
    P[(size_t)p * 64 + lane + 32] = a1;
}

// ---------------------------------------------------------------------------
// Decode: one thread per query, packed f32x2, register-budgeted:
// layer-2 output computed in two 32-wide halves so live state is
// h0p[32] (64 regs) + h1p[16] (32 regs). Same total LDS traffic.
// ---------------------------------------------------------------------------
__global__ void __launch_bounds__(256, 2)
decode_kernel(const float* __restrict__ P, const float* __restrict__ coords,
              const float* __restrict__ cells, const float* __restrict__ mw0,
              const float* __restrict__ mw1, const float* __restrict__ mb1,
              const float* __restrict__ mw2, const float* __restrict__ mb2,
              float* __restrict__ out)
{
    __shared__ __align__(16) float sw1[64 * 64];
    __shared__ __align__(16) float sw0e[6 * 64];
    __shared__ __align__(16) float sb1[64];
    __shared__ float sw2[64];
    __shared__ float sb2s;
    int tid = threadIdx.x;
    for (int i = tid; i < 64 * 64; i += 256) sw1[i] = mw1[i];
    for (int i = tid; i < 6 * 64; i += 256) sw0e[i] = mw0[96 * 64 + i];
    if (tid < 64) { sb1[tid] = mb1[tid]; sw2[tid] = mw2[tid]; }
    if (tid == 0) sb2s = mb2[0];
    __syncthreads();

    int q = blockIdx.x * 256 + tid;  // 294912 = 1152 * 256 exact
    int b = q / (HQ * HQ);
    float cy = coords[2 * q], cx = coords[2 * q + 1];
    float clh = cells[2 * q] * (float)Hh, clw = cells[2 * q + 1] * (float)Ww;
    const float rr = 1.0f / (float)Hh;

    float preds[4], areas[4];
#pragma unroll 1
    for (int corner = 0; corner < 4; corner++) {
        float vy = (corner & 2) ? 1.0f : -1.0f;
        float vx = (corner & 1) ? 1.0f : -1.0f;
        float ccy = fminf(fmaxf(cy + vy * rr + EPSK, -1.0f + EPSK), 1.0f - EPSK);
        float ccx = fminf(fmaxf(cx + vx * rr + EPSK, -1.0f + EPSK), 1.0f - EPSK);
        int iy = (int)rintf((ccy + 1.0f) * (float)Hh / 2.0f - 0.5f);
        int ix = (int)rintf((ccx + 1.0f) * (float)Ww / 2.0f - 0.5f);
        iy = min(max(iy, 0), Hh - 1);
        ix = min(max(ix, 0), Ww - 1);
        float sampy = ((iy + 0.5f) / (float)Hh) * 2.0f - 1.0f;
        float sampx = ((ix + 0.5f) / (float)Ww) * 2.0f - 1.0f;
        float rely = (cy - sampy) * (float)Hh;
        float relx = (cx - sampx) * (float)Ww;

        // h0 = gathered P + extras (packed pairs over hidden index)
        u64 h0p[32];
        const ulonglong2* p4 =
            (const ulonglong2*)(P + (((size_t)b * Hh + iy) * Ww + ix) * 64);
#pragma unroll
        for (int j = 0; j < 16; j++) {
            ulonglong2 v = p4[j];
            h0p[2 * j] = v.x;
            h0p[2 * j + 1] = v.y;
        }
        float xs[6] = {rely, relx, cy, cx, clh, clw};
#pragma unroll
        for (int e = 0; e < 6; e++) {
            u64 xp = pack2(xs[e], xs[e]);
            const ulonglong2* wp = (const ulonglong2*)(sw0e + e * 64);
#pragma unroll
            for (int j = 0; j < 16; j++) {
                ulonglong2 w = wp[j];
                fma2(h0p[2 * j], xp, w.x);
                fma2(h0p[2 * j + 1], xp, w.y);
            }
        }
        // layer 2 in two 32-wide output halves (register budget)
        float pr = sb2s;
#pragma unroll 1
        for (int half = 0; half < 2; half++) {
            u64 h1p[16];
            const ulonglong2* bp = (const ulonglong2*)(sb1 + half * 32);
#pragma unroll
            for (int j = 0; j < 8; j++) {
                ulonglong2 v = bp[j];
                h1p[2 * j] = v.x;
                h1p[2 * j + 1] = v.y;
            }
#pragma unroll 4
            for (int kp = 0; kp < 32; kp++) {
                float lo, hi;
                unpack2(lo, hi, h0p[kp]);
                float xa = fmaxf(lo, 0.0f), xb = fmaxf(hi, 0.0f);
                u64 xpa = pack2(xa, xa), xpb = pack2(xb, xb);
                const ulonglong2* wra =
                    (const ulonglong2*)(sw1 + (2 * kp) * 64 + half * 32);
                const ulonglong2* wrb =
                    (const ulonglong2*)(sw1 + (2 * kp + 1) * 64 + half * 32);
#pragma unroll
                for (int j = 0; j < 8; j++) {
                    ulonglong2 w = wra[j];
                    fma2(h1p[2 * j], xpa, w.x);
                    fma2(h1p[2 * j + 1], xpa, w.y);
                }
#pragma unroll
                for (int j = 0; j < 8; j++) {
                    ulonglong2 w = wrb[j];
                    fma2(h1p[2 * j], xpb, w.x);
                    fma2(h1p[2 * j + 1], xpb, w.y);
                }
            }
            const float* w2h = sw2 + half * 32;
#pragma unroll
            for (int j = 0; j < 16; j++) {
                float a, c;
                unpack2(a, c, h1p[j]);
                pr += fmaxf(a, 0.0f) * w2h[2 * j] + fmaxf(c, 0.0f) * w2h[2 * j + 1];
            }
        }
        preds[corner] = pr;
        areas[corner] = fabsf(rely * relx) + EPSK;
    }
    float num = preds[0] * areas[3] + preds[1] * areas[2] +
                preds[2] * areas[1] + preds[3] * areas[0];
    float den = areas[0] + areas[1] + areas[2] + areas[3];
    out[q] = num / den;
}

// ---------------------------------------------------------------------------
extern "C" void kernel_launch(void* const* d_in, const int* in_sizes, int n_in,
                              void* d_out, int out_size)
{
    const float* feats2  = (const float*)d_in[0];
    const float* feats4  = (const float*)d_in[1];
    const float* feats32 = (const float*)d_in[2];
    const float* coords  = (const float*)d_in[3];
    const float* cells   = (const float*)d_in[4];
    const float* w2  = (const float*)d_in[5];
    const float* b2  = (const float*)d_in[6];
    const float* w4  = (const float*)d_in[7];
    const float* b4  = (const float*)d_in[8];
    const float* w32 = (const float*)d_in[9];
    const float* b32 = (const float*)d_in[10];
    const float* wf  = (const float*)d_in[11];
    const float* bf  = (const float*)d_in[12];
    const float* mw0 = (const float*)d_in[13];
    const float* mb0 = (const float*)d_in[14];
    const float* mw1 = (const float*)d_in[15];
    const float* mb1 = (const float*)d_in[16];
    const float* mw2 = (const float*)d_in[17];
    const float* mb2 = (const float*)d_in[18];
    float* out = (float*)d_out;

    float *a4p, *a32p, *Xp, *asppp, *Pp;
    cudaGetSymbolAddress((void**)&a4p, g_a4);
    cudaGetSymbolAddress((void**)&a32p, g_a32);
    cudaGetSymbolAddress((void**)&Xp, g_X);
    cudaGetSymbolAddress((void**)&asppp, g_aspp);
    cudaGetSymbolAddress((void**)&Pp, g_P);

    // 1x1 convs (a2 goes straight into the concat buffer, channels 0..31)
    conv1x1_kernel<<<9216, 256, 64 * 32 * 4>>>(feats2, w2, b2, Xp, 73728, 64, 96, 0);
    conv1x1_kernel<<<2304, 256, 96 * 32 * 4>>>(feats4, w4, b4, a4p, 18432, 96, 32, 0);
    conv1x1_kernel<<<144, 256, 160 * 32 * 4>>>(feats32, w32, b32, a32p, 1152, 160, 32, 0);

    // bilinear upsample into concat channels 32..63 and 64..95
    upsample_kernel<<<2304, 256>>>(a4p, Xp, 96, 96, 32);
    upsample_kernel<<<2304, 256>>>(a32p, Xp, 24, 24, 64);

    // 3x3 conv + ReLU (packed f32x2, 16x8 tile, 256 threads)
    dim3 g3(24, 12, 6);
    conv3x3_kernel<<<g3, 256>>>(Xp, wf, bf, asppp);

    // per-pixel projection through MLP layer-1 feature block
    proj_kernel<<<9216, 256>>>(asppp, mw0, mb0, Pp);

    // per-query 4-corner decode + blend (packed f32x2, register-budgeted)
    decode_kernel<<<1152, 256>>>(Pp, coords, cells, mw0, mw1, mb1, mw2, mb2, out);
}